// round 15
// baseline (speedup 1.0000x reference)
#include <cuda_runtime.h>
#include <math.h>

#define TPB 512

namespace FN {

constexpr int NE = 16;

// per-batch arena
struct __align__(16) SmemB {
  float one[NE * 260];   // one-stream activations
  float two[256 * 36];   // two-stream activations, row (i*16+j)
  float two4[256 * 5];   // layer-0 two features } det arena alias (2240 floats)
  float f0s[16 * 60];    // layer-0 f vectors    }
  float g1all[512];      // [0:256)=g1u, [256:512)=g1d
  float g2u[512], g2d[512];
  float c[256];
  float xx[48], rr[64];
};
// shared arena
struct __align__(16) SmemS {
  float wt[2 * 16 * 260];  // double-buffered weight tiles, transposed [fi][o]
  float wwt[32 * 36];      // two-stream weights transposed [f][o]
  float bw[32];
  float pos[16];
  float sg[512], pw[512], eg[128];
};

// named barriers:
//  1: g2 ready        (aux 256 arrive + gemm 128 sync = 384)
//  2: aux-internal    (256)
//  3: f0s ready       (aux 256 arrive + gemm 128 sync = 384)
//  5: one ready       (gemm 128 arrive + aux 256 sync = 384)
//  6: c ready         (aux 256 arrive + gemm 128 sync = 384)
//  8,9:  ready[b]     (staging 128 arrive + gemm 128 sync = 256)
//  10,11: free[b]     (gemm 128 arrive + staging 128 sync = 256)
#define BARS(ID, CNT) asm volatile("bar.sync %0, %1;" :: "r"(ID), "r"(CNT) : "memory")
#define BARA(ID, CNT) asm volatile("bar.arrive %0, %1;" :: "r"(ID), "r"(CNT) : "memory")

__device__ __forceinline__ float ftanh(float x) {
  float ax = fabsf(x);
  float e = __expf(-2.0f * ax);
  float t = __fdividef(1.0f - e, 1.0f + e);
  return x >= 0.0f ? t : -t;
}

#define RF4(P, AV) do { \
  (P)[0] = fmaf(AV.x, w0.x, (P)[0]); \
  (P)[1] = fmaf(AV.x, w0.y, (P)[1]); \
  (P)[2] = fmaf(AV.x, w0.z, (P)[2]); \
  (P)[3] = fmaf(AV.x, w0.w, (P)[3]); \
  (P)[0] = fmaf(AV.y, w1.x, (P)[0]); \
  (P)[1] = fmaf(AV.y, w1.y, (P)[1]); \
  (P)[2] = fmaf(AV.y, w1.z, (P)[2]); \
  (P)[3] = fmaf(AV.y, w1.w, (P)[3]); \
  (P)[0] = fmaf(AV.z, w2.x, (P)[0]); \
  (P)[1] = fmaf(AV.z, w2.y, (P)[1]); \
  (P)[2] = fmaf(AV.z, w2.z, (P)[2]); \
  (P)[3] = fmaf(AV.z, w2.w, (P)[3]); \
  (P)[0] = fmaf(AV.w, w3.x, (P)[0]); \
  (P)[1] = fmaf(AV.w, w3.y, (P)[1]); \
  (P)[2] = fmaf(AV.w, w3.z, (P)[2]); \
  (P)[3] = fmaf(AV.w, w3.w, (P)[3]); \
} while (0)

// E8xO4 dual-batch GEMM tile: 8 electrons x 4 outputs x 2 batches per thread.
template<int KT, int AS>
__device__ __forceinline__ void one_tile_e8(const float* buf,
                                            const float* actA, const float* actB,
                                            int ob, float* accA, float* accB) {
#pragma unroll
  for (int q = 0; q < KT / 4; q++) {
    float4 w0 = *(const float4*)(buf + (q * 4 + 0) * 260 + ob);
    float4 w1 = *(const float4*)(buf + (q * 4 + 1) * 260 + ob);
    float4 w2 = *(const float4*)(buf + (q * 4 + 2) * 260 + ob);
    float4 w3 = *(const float4*)(buf + (q * 4 + 3) * 260 + ob);
#pragma unroll
    for (int r = 0; r < 8; r++) {
      float4 a = *(const float4*)(actA + r * AS + q * 4);
      RF4(accA + r * 4, a);
      a = *(const float4*)(actB + r * AS + q * 4);
      RF4(accB + r * 4, a);
    }
  }
}

__global__ void __launch_bounds__(TPB, 1)
ferminet_kernel(const float* __restrict__ x, const float* __restrict__ nuc,
                const float* __restrict__ v0w, const float* __restrict__ v0b,
                const float* __restrict__ vw,  const float* __restrict__ vb,
                const float* __restrict__ w0w, const float* __restrict__ w0b,
                const float* __restrict__ ww,  const float* __restrict__ wb,
                const float* __restrict__ envw, const float* __restrict__ envg,
                const float* __restrict__ sigma, const float* __restrict__ pi,
                float* __restrict__ out) {
  extern __shared__ float smem_raw[];
  SmemS* SS = (SmemS*)smem_raw;
  SmemB* P0 = (SmemB*)(smem_raw + sizeof(SmemS) / 4);
  SmemB* P1 = P0 + 1;
  const int tid = threadIdx.x;
  const int half = tid >> 8;       // 0 = GEMM+staging, 1 = AUX
  const int th = tid & 255;
  const int b0 = blockIdx.x * 2;
  const int b1 = b0 + 1;

  // ---- Phase A: smalls (all 512) ----
  if (tid < 48) P0->xx[tid] = x[b0 * 48 + tid];
  else if (tid >= 64 && tid < 112) P1->xx[tid - 64] = x[b1 * 48 + tid - 64];
  if (tid < 12) SS->pos[tid] = nuc[tid];
  {
    int q = tid;  // (k*8+i)*4+m, i<8; global = q + (q>>5)*32
    SS->sg[q] = fabsf(sigma[q + (q >> 5) * 32]);
    SS->pw[q] = pi[q + (q >> 5) * 32];
  }
  if (tid < 128) SS->eg[tid] = envg[(tid >> 3) * NE + (tid & 7)];
  __syncthreads();

  // ---- Phase B: geometry (each 256-half does its own batch) ----
  {
    SmemB* P = half ? P1 : P0;
    int i = th >> 4, j = th & 15;
    float dx = P->xx[j * 3 + 0] - P->xx[i * 3 + 0];
    float dy = P->xx[j * 3 + 1] - P->xx[i * 3 + 1];
    float dz = P->xx[j * 3 + 2] - P->xx[i * 3 + 2];
    float ss = dx * dx + dy * dy + dz * dz;
    float nr = ss > 0.0f ? sqrtf(ss) : 0.0f;
    float* t4 = P->two4 + th * 5;
    t4[0] = dx; t4[1] = dy; t4[2] = dz; t4[3] = nr;
    if (th < 64) {
      int n = th >> 2, m = th & 3;
      float ex = P->xx[n * 3 + 0] - SS->pos[m * 3 + 0];
      float ey = P->xx[n * 3 + 1] - SS->pos[m * 3 + 1];
      float ez = P->xx[n * 3 + 2] - SS->pos[m * 3 + 2];
      float d = sqrtf(ex * ex + ey * ey + ez * ez);
      float* o1 = P->one + n * 260 + m * 4;
      o1[0] = ex; o1[1] = ey; o1[2] = ez; o1[3] = d;
      P->rr[n * 4 + m] = d;
    }
  }
  __syncthreads();

  // ============== DIVERGENT REGION ==============
  if (tid < 128) {
    // ---------- GEMM warps (E8 x O4, dual batch) ----------
    const int g = tid >> 6;          // 0/1: electron octet
    const int ob = (tid & 63) * 4;   // output base
    float accA[32], accB[32];
    // ---- Layer 0 (7 tiles, KT=8, acts = f0s) ----
#pragma unroll
    for (int q = 0; q < 32; q++) { accA[q] = 0.0f; accB[q] = 0.0f; }
    BARS(3, 384);  // f0s ready
    for (int gt = 0; gt < 7; gt++) {
      BARS(8 + (gt & 1), 256);
      const float* cur = SS->wt + (gt & 1) * 4160;
      one_tile_e8<8, 60>(cur, P0->f0s + g * 480 + gt * 8,
                         P1->f0s + g * 480 + gt * 8, ob, accA, accB);
      BARA(10 + (gt & 1), 256);
    }
    {
      float4 bb = *(const float4*)(v0b + ob);
#pragma unroll
      for (int r = 0; r < 8; r++) {
        int n = g * 8 + r;
        float4 v;
        v.x = ftanh(accA[r * 4 + 0] + bb.x); v.y = ftanh(accA[r * 4 + 1] + bb.y);
        v.z = ftanh(accA[r * 4 + 2] + bb.z); v.w = ftanh(accA[r * 4 + 3] + bb.w);
        *(float4*)(P0->one + n * 260 + ob) = v;
        v.x = ftanh(accB[r * 4 + 0] + bb.x); v.y = ftanh(accB[r * 4 + 1] + bb.y);
        v.z = ftanh(accB[r * 4 + 2] + bb.z); v.w = ftanh(accB[r * 4 + 3] + bb.w);
        *(float4*)(P1->one + n * 260 + ob) = v;
      }
    }
    __threadfence_block();
    BARA(5, 384);  // one(l0) ready
    // ---- Layers 1..3 (20 tiles each, KT=16) ----
    for (int l = 1; l < 4; l++) {
#pragma unroll
      for (int q = 0; q < 32; q++) { accA[q] = 0.0f; accB[q] = 0.0f; }
      for (int T = 0; T < 20; T++) {
        int gt = 7 + (l - 1) * 20 + T;
        BARS(8 + (gt & 1), 256);
        if (T == 16) BARS(1, 384);  // g2 ready
        const float* cur = SS->wt + (gt & 1) * 4160;
        if (T < 16) {
          one_tile_e8<16, 260>(cur, P0->one + g * 8 * 260 + T * 16,
                               P1->one + g * 8 * 260 + T * 16, ob, accA, accB);
        } else {
          int off2 = g * 8 * 32 + ((T & 1) ? 16 : 0);
          const float* aA = ((T < 18) ? P0->g2u : P0->g2d) + off2;
          const float* aB = ((T < 18) ? P1->g2u : P1->g2d) + off2;
          one_tile_e8<16, 32>(cur, aA, aB, ob, accA, accB);
        }
        BARA(10 + (gt & 1), 256);
      }
      BARS(6, 384);  // c ready
      {
        float4 cA = *(const float4*)(P0->c + ob);
        float4 cB = *(const float4*)(P1->c + ob);
#pragma unroll
        for (int r = 0; r < 8; r++) {
          int n = g * 8 + r;
          float4 old = *(const float4*)(P0->one + n * 260 + ob);
          float4 v;
          v.x = ftanh(accA[r * 4 + 0] + cA.x) + old.x;
          v.y = ftanh(accA[r * 4 + 1] + cA.y) + old.y;
          v.z = ftanh(accA[r * 4 + 2] + cA.z) + old.z;
          v.w = ftanh(accA[r * 4 + 3] + cA.w) + old.w;
          *(float4*)(P0->one + n * 260 + ob) = v;
          old = *(const float4*)(P1->one + n * 260 + ob);
          v.x = ftanh(accB[r * 4 + 0] + cB.x) + old.x;
          v.y = ftanh(accB[r * 4 + 1] + cB.y) + old.y;
          v.z = ftanh(accB[r * 4 + 2] + cB.z) + old.z;
          v.w = ftanh(accB[r * 4 + 3] + cB.w) + old.w;
          *(float4*)(P1->one + n * 260 + ob) = v;
        }
      }
      __threadfence_block();
      if (l < 3) BARA(5, 384);
    }
  } else if (tid < 256) {
    // ---------- STAGING warps: weight tiles via ready/free ring ----------
    const int ths = tid - 128;
    for (int gt = 0; gt < 67; gt++) {
      if (gt >= 2) BARS(10 + (gt & 1), 256);  // wait buffer free
      float* buf = SS->wt + (gt & 1) * 4160;
      if (gt < 7) {
        // layer0: KT=8, 56 real cols, zero-pad
#pragma unroll
        for (int e = 0; e < 16; e++) {
          int idx = ths + e * 128;
          int o = idx >> 3, fi = idx & 7;
          int col = gt * 8 + fi;
          buf[fi * 260 + o] = (col < 56) ? __ldg(v0w + o * 56 + col) : 0.0f;
        }
      } else {
        int l = (gt - 7) / 20, T = (gt - 7) % 20;
        const float* Wv = vw + l * (256 * 832);
        int f0 = (T < 16) ? T * 16 : 768 + (T - 16) * 16;
#pragma unroll
        for (int e = 0; e < 8; e++) {
          int j = ths + e * 128;
          int o = j >> 2, fq = j & 3;
          float4 v = __ldg((const float4*)(Wv + o * 832 + f0 + fq * 4));
          buf[(fq * 4 + 0) * 260 + o] = v.x;
          buf[(fq * 4 + 1) * 260 + o] = v.y;
          buf[(fq * 4 + 2) * 260 + o] = v.z;
          buf[(fq * 4 + 3) * 260 + o] = v.w;
        }
      }
      __threadfence_block();
      BARA(8 + (gt & 1), 256);  // buffer ready
    }
  } else {
    // ---------- AUX warps (256 threads, th = tid-256) ----------
    const int pg = th >> 2;        // two-stream pair group
    const int og = (th & 3) * 8;   // two-stream output base
    // ---- Layer 0 ----
    {
#pragma unroll
      for (int bi = 0; bi < 2; bi++) {
        SmemB* P = bi ? P1 : P0;
        if (th < 32) {  // g1 means over 16-dim raw one
          int f = th & 15; bool up = th < 16;
          float s = 0.0f;
#pragma unroll
          for (int n = 0; n < 8; n++) s += P->one[(up ? n : n + 8) * 260 + f];
          P->g1all[(up ? 0 : 256) + f] = s * 0.125f;
        }
        if (th < 128) {  // g2 means over 4-dim two4
          int i = th >> 3, c2 = th & 7;
          int col = c2 & 3; bool up2 = c2 < 4;
          float s = 0.0f;
#pragma unroll
          for (int j = 0; j < 8; j++) s += P->two4[(i * NE + (up2 ? j : j + 8)) * 5 + col];
          (up2 ? P->g2u : P->g2d)[i * 32 + col] = s * 0.125f;
        }
      }
      if (th < 128) SS->wwt[(th & 3) * 36 + (th >> 2)] = __ldg(w0w + th);
      if (th < 32) SS->bw[th] = __ldg(w0b + th);
      BARS(2, 256);  // aux-internal
      // build f0s [16][60] per batch
#pragma unroll
      for (int bi = 0; bi < 2; bi++) {
        SmemB* P = bi ? P1 : P0;
#pragma unroll
        for (int e = 0; e < 4; e++) {
          int idx = th + e * 256;
          if (idx < 960) {
            int n = idx / 60, cc = idx - n * 60;
            float v;
            if (cc < 16)      v = P->one[n * 260 + cc];
            else if (cc < 32) v = P->g1all[cc - 16];
            else if (cc < 48) v = P->g1all[256 + cc - 32];
            else if (cc < 52) v = P->g2u[n * 32 + (cc - 48)];
            else if (cc < 56) v = P->g2d[n * 32 + (cc - 52)];
            else              v = 0.0f;
            P->f0s[idx] = v;
          }
        }
      }
      __threadfence_block();
      BARA(3, 384);  // f0s -> gemm
      // two-stream layer 0 (K=4), both batches
#pragma unroll
      for (int bi = 0; bi < 2; bi++) {
        SmemB* P = bi ? P1 : P0;
        float acc2[32];
#pragma unroll
        for (int q = 0; q < 32; q++) acc2[q] = 0.0f;
#pragma unroll
        for (int f = 0; f < 4; f++) {
          float4 w0v = *(const float4*)(SS->wwt + f * 36 + og);
          float4 w1v = *(const float4*)(SS->wwt + f * 36 + og + 4);
#pragma unroll
          for (int r = 0; r < 4; r++) {
            float av = P->two4[(r * 64 + pg) * 5 + f];
            acc2[r*8+0] = fmaf(av, w0v.x, acc2[r*8+0]);
            acc2[r*8+1] = fmaf(av, w0v.y, acc2[r*8+1]);
            acc2[r*8+2] = fmaf(av, w0v.z, acc2[r*8+2]);
            acc2[r*8+3] = fmaf(av, w0v.w, acc2[r*8+3]);
            acc2[r*8+4] = fmaf(av, w1v.x, acc2[r*8+4]);
            acc2[r*8+5] = fmaf(av, w1v.y, acc2[r*8+5]);
            acc2[r*8+6] = fmaf(av, w1v.z, acc2[r*8+6]);
            acc2[r*8+7] = fmaf(av, w1v.w, acc2[r*8+7]);
          }
        }
        float4 bb0 = *(const float4*)(SS->bw + og);
        float4 bb1 = *(const float4*)(SS->bw + og + 4);
#pragma unroll
        for (int r = 0; r < 4; r++) {
          float* rowp = P->two + (r * 64 + pg) * 36 + og;
          float4 v0, v1;
          v0.x = ftanh(acc2[r*8+0] + bb0.x); v0.y = ftanh(acc2[r*8+1] + bb0.y);
          v0.z = ftanh(acc2[r*8+2] + bb0.z); v0.w = ftanh(acc2[r*8+3] + bb0.w);
          v1.x = ftanh(acc2[r*8+4] + bb1.x); v1.y = ftanh(acc2[r*8+5] + bb1.y);
          v1.z = ftanh(acc2[r*8+6] + bb1.z); v1.w = ftanh(acc2[r*8+7] + bb1.w);
          *(float4*)(rowp) = v0;
          *(float4*)(rowp + 4) = v1;
        }
      }
    }
    // ---- Layers 1..3 ----
    for (int l = 1; l < 4; l++) {
      const float* Wv = vw + (l - 1) * (256 * 832);
      BARS(5, 384);  // one(l-1) ready
#pragma unroll
      for (int bi = 0; bi < 2; bi++) {
        SmemB* P = bi ? P1 : P0;
        float su = 0.0f, sd = 0.0f;
#pragma unroll
        for (int n = 0; n < 8; n++) {
          su += P->one[n * 260 + th];
          sd += P->one[(n + 8) * 260 + th];
        }
        P->g1all[th] = su * 0.125f;
        P->g1all[256 + th] = sd * 0.125f;
#pragma unroll
        for (int rep = 0; rep < 2; rep++) {
          int idx = th + rep * 256;
          int i = idx >> 5, o = idx & 31;
          float a = 0.0f, bb = 0.0f;
#pragma unroll
          for (int j = 0; j < 8; j++) {
            a  += P->two[(i * NE + j) * 36 + o];
            bb += P->two[(i * NE + j + 8) * 36 + o];
          }
          P->g2u[i * 32 + o] = a * 0.125f;
          P->g2d[i * 32 + o] = bb * 0.125f;
        }
      }
      {
        const float* Ww = ww + (l - 1) * 1024;
#pragma unroll
        for (int e = 0; e < 4; e++) {
          int idx = th + e * 256;
          SS->wwt[(idx & 31) * 36 + (idx >> 5)] = __ldg(Ww + idx);
        }
        if (th < 32) SS->bw[th] = __ldg(wb + (l - 1) * 32 + th);
      }
      BARS(2, 256);          // aux-internal: means + wwt visible
      __threadfence_block();
      BARA(1, 384);          // g2 -> gemm
      // dual c-projection (coalesced LDG + shuffle reduce)
      {
        int warp = th >> 5, lane = th & 31;
        float4 ga0 = *(const float4*)(P0->g1all + 0 * 128 + lane * 4);
        float4 ga1 = *(const float4*)(P0->g1all + 1 * 128 + lane * 4);
        float4 ga2 = *(const float4*)(P0->g1all + 2 * 128 + lane * 4);
        float4 ga3 = *(const float4*)(P0->g1all + 3 * 128 + lane * 4);
        float4 gb0 = *(const float4*)(P1->g1all + 0 * 128 + lane * 4);
        float4 gb1 = *(const float4*)(P1->g1all + 1 * 128 + lane * 4);
        float4 gb2 = *(const float4*)(P1->g1all + 2 * 128 + lane * 4);
        float4 gb3 = *(const float4*)(P1->g1all + 3 * 128 + lane * 4);
#pragma unroll 2
        for (int rr = 0; rr < 32; rr++) {
          int row = warp * 32 + rr;
          const float* wrow = Wv + row * 832 + 256 + lane * 4;
          float4 w0 = __ldg((const float4*)(wrow));
          float4 w1 = __ldg((const float4*)(wrow + 128));
          float4 w2 = __ldg((const float4*)(wrow + 256));
          float4 w3 = __ldg((const float4*)(wrow + 384));
          float sA = w0.x*ga0.x + w0.y*ga0.y + w0.z*ga0.z + w0.w*ga0.w
                   + w1.x*ga1.x + w1.y*ga1.y + w1.z*ga1.z + w1.w*ga1.w
                   + w2.x*ga2.x + w2.y*ga2.y + w2.z*ga2.z + w2.w*ga2.w
                   + w3.x*ga3.x + w3.y*ga3.y + w3.z*ga3.z + w3.w*ga3.w;
          float sB = w0.x*gb0.x + w0.y*gb0.y + w0.z*gb0.z + w0.w*gb0.w
                   + w1.x*gb1.x + w1.y*gb1.y + w1.z*gb1.z + w1.w*gb1.w
                   + w2.x*gb2.x + w2.y*gb2.y + w2.z*gb2.z + w2.w*gb2.w
                   + w3.x*gb3.x + w3.y*gb3.y + w3.z*gb3.z + w3.w*gb3.w;
#pragma unroll
          for (int off = 16; off; off >>= 1) {
            sA += __shfl_xor_sync(0xffffffffu, sA, off);
            sB += __shfl_xor_sync(0xffffffffu, sB, off);
          }
          if (lane == 0) {
            float bv = __ldg(vb + (l - 1) * 256 + row);
            P0->c[row] = sA + bv;
            P1->c[row] = sB + bv;
          }
        }
      }
      __threadfence_block();
      BARA(6, 384);  // c -> gemm
      // two-stream GEMM (K=32) + residual, both batches
#pragma unroll
      for (int bi = 0; bi < 2; bi++) {
        SmemB* P = bi ? P1 : P0;
        float acc2[32];
#pragma unroll
        for (int q = 0; q < 32; q++) acc2[q] = 0.0f;
#pragma unroll
        for (int f4 = 0; f4 < 8; f4++) {
          float4 a0 = *(const float4*)(P->two + (0 * 64 + pg) * 36 + f4 * 4);
          float4 a1 = *(const float4*)(P->two + (1 * 64 + pg) * 36 + f4 * 4);
          float4 a2 = *(const float4*)(P->two + (2 * 64 + pg) * 36 + f4 * 4);
          float4 a3 = *(const float4*)(P->two + (3 * 64 + pg) * 36 + f4 * 4);
#pragma unroll
          for (int k = 0; k < 4; k++) {
            int f = f4 * 4 + k;
            float4 wA = *(const float4*)(SS->wwt + f * 36 + og);
            float4 wB = *(const float4*)(SS->wwt + f * 36 + og + 4);
            float v0 = (k == 0) ? a0.x : (k == 1) ? a0.y : (k == 2) ? a0.z : a0.w;
            float v1 = (k == 0) ? a1.x : (k == 1) ? a1.y : (k == 2) ? a1.z : a1.w;
            float v2 = (k == 0) ? a2.x : (k == 1) ? a2.y : (k == 2) ? a2.z : a2.w;
            float v3 = (k == 0) ? a3.x : (k == 1) ? a3.y : (k == 2) ? a3.z : a3.w;
#define TWO_FMA(RR, AV) \
            acc2[(RR)*8+0] = fmaf(AV, wA.x, acc2[(RR)*8+0]); \
            acc2[(RR)*8+1] = fmaf(AV, wA.y, acc2[(RR)*8+1]); \
            acc2[(RR)*8+2] = fmaf(AV, wA.z, acc2[(RR)*8+2]); \
            acc2[(RR)*8+3] = fmaf(AV, wA.w, acc2[(RR)*8+3]); \
            acc2[(RR)*8+4] = fmaf(AV, wB.x, acc2[(RR)*8+4]); \
            acc2[(RR)*8+5] = fmaf(AV, wB.y, acc2[(RR)*8+5]); \
            acc2[(RR)*8+6] = fmaf(AV, wB.z, acc2[(RR)*8+6]); \
            acc2[(RR)*8+7] = fmaf(AV, wB.w, acc2[(RR)*8+7]);
            TWO_FMA(0, v0) TWO_FMA(1, v1) TWO_FMA(2, v2) TWO_FMA(3, v3)
#undef TWO_FMA
          }
        }
        __syncwarp();  // row-sharing threads are warp-local
        float4 bb0 = *(const float4*)(SS->bw + og);
        float4 bb1 = *(const float4*)(SS->bw + og + 4);
#pragma unroll
        for (int r = 0; r < 4; r++) {
          float* rowp = P->two + (r * 64 + pg) * 36 + og;
          float4 o0 = *(const float4*)(rowp);
          float4 o1 = *(const float4*)(rowp + 4);
          o0.x = ftanh(acc2[r*8+0] + bb0.x) + o0.x;
          o0.y = ftanh(acc2[r*8+1] + bb0.y) + o0.y;
          o0.z = ftanh(acc2[r*8+2] + bb0.z) + o0.z;
          o0.w = ftanh(acc2[r*8+3] + bb0.w) + o0.w;
          o1.x = ftanh(acc2[r*8+4] + bb1.x) + o1.x;
          o1.y = ftanh(acc2[r*8+5] + bb1.y) + o1.y;
          o1.z = ftanh(acc2[r*8+6] + bb1.z) + o1.z;
          o1.w = ftanh(acc2[r*8+7] + bb1.w) + o1.w;
          *(float4*)(rowp) = o0;
          *(float4*)(rowp + 4) = o1;
        }
        __syncwarp();
      }
    }
  }
  // ============== END DIVERGENT REGION ==============
  __syncthreads();

  // ---- Envelope / orbitals (each 256-half: its own batch) ----
  {
    SmemB* P = half ? P1 : P0;
    int k = th >> 4, i = (th >> 1) & 7, jh = th & 1;
    const float* wrow = envw + (k * 16 + i) * 256;
    float acc[8];
#pragma unroll
    for (int j = 0; j < 8; j++) acc[j] = 0.0f;
    for (int f4 = 0; f4 < 64; f4++) {
      float4 w = __ldg((const float4*)(wrow + f4 * 4));
#pragma unroll
      for (int j = 0; j < 8; j++) {
        float4 a = *(const float4*)(P->one + (jh * 8 + j) * 260 + f4 * 4);
        acc[j] += w.x * a.x + w.y * a.y + w.z * a.z + w.w * a.w;
      }
    }
    float lg = 256.0f * SS->eg[k * 8 + i];
    int si = (k * 8 + i) * 4;
    float p0 = SS->pw[si], p1 = SS->pw[si + 1], p2 = SS->pw[si + 2], p3 = SS->pw[si + 3];
    float s0 = SS->sg[si], s1 = SS->sg[si + 1], s2 = SS->sg[si + 2], s3 = SS->sg[si + 3];
#pragma unroll
    for (int j = 0; j < 8; j++) {
      int col = jh * 8 + j;
      const float* rrow = P->rr + col * 4;
      float env = p0 * __expf(-s0 * rrow[0]) + p1 * __expf(-s1 * rrow[1]) +
                  p2 * __expf(-s2 * rrow[2]) + p3 * __expf(-s3 * rrow[3]);
      P->two4[(jh * 16 + k) * 65 + i * 8 + j] = (acc[j] + lg) * env;
    }
  }
  __syncthreads();

  // ---- Determinants: 32 matrices 8x8 per batch, pivoted LU ----
  {
    SmemB* P = half ? P1 : P0;
    float* D = P->two4;
    if (th < 32) {
      float* A = D + th * 65;
      float dv = 1.0f;
      for (int cph = 0; cph < 8; cph++) {
        int p = cph; float mx = fabsf(A[cph * 8 + cph]);
        for (int r = cph + 1; r < 8; r++) {
          float fv = fabsf(A[r * 8 + cph]);
          if (fv > mx) { mx = fv; p = r; }
        }
        if (mx == 0.0f) { dv = 0.0f; break; }
        if (p != cph) {
#pragma unroll
          for (int cc = 0; cc < 8; cc++) {
            float t = A[cph * 8 + cc]; A[cph * 8 + cc] = A[p * 8 + cc]; A[p * 8 + cc] = t;
          }
          dv = -dv;
        }
        float piv = A[cph * 8 + cph];
        dv *= piv;
        float inv = 1.0f / piv;
        for (int r = cph + 1; r < 8; r++) {
          float m = A[r * 8 + cph] * inv;
          for (int cc = cph + 1; cc < 8; cc++) A[r * 8 + cc] -= m * A[cph * 8 + cc];
        }
      }
      (D + 2080)[th] = dv;
      __syncwarp();
      if (th < 16) (D + 2112)[th] = (D + 2080)[th] * (D + 2080)[16 + th];
      __syncwarp();
      if (th == 0) {
        float s = 0.0f;
#pragma unroll
        for (int k = 0; k < 16; k++) s += (D + 2112)[k];
        out[half ? b1 : b0] = s;
      }
    }
  }
}

}  // namespace FN

extern "C" void kernel_launch(void* const* d_in, const int* in_sizes, int n_in,
                              void* d_out, int out_size) {
  const float* x    = (const float*)d_in[0];
  const float* nuc  = (const float*)d_in[1];
  const float* v0w  = (const float*)d_in[2];
  const float* v0b  = (const float*)d_in[3];
  const float* vw   = (const float*)d_in[4];
  const float* vb   = (const float*)d_in[5];
  const float* w0w  = (const float*)d_in[6];
  const float* w0b  = (const float*)d_in[7];
  const float* ww   = (const float*)d_in[8];
  const float* wb   = (const float*)d_in[9];
  const float* envw = (const float*)d_in[10];
  const float* envg = (const float*)d_in[11];
  const float* sig  = (const float*)d_in[12];
  const float* pi   = (const float*)d_in[13];
  float* out = (float*)d_out;

  int B = in_sizes[0] / 48;
  int smem = (int)(sizeof(FN::SmemS) + 2 * sizeof(FN::SmemB));
  cudaFuncSetAttribute(FN::ferminet_kernel, cudaFuncAttributeMaxDynamicSharedMemorySize, smem);
  FN::ferminet_kernel<<<B / 2, TPB, smem>>>(x, nuc, v0w, v0b, vw, vb, w0w, w0b, ww, wb,
                                            envw, envg, sig, pi, out);
}